// round 5
// baseline (speedup 1.0000x reference)
#include <cuda_runtime.h>
#include <cstdint>

#define T_STEPS 512

// Scratch (allocation-free rule: __device__ globals)
// proj[bucket][lane] = (Pi*0.5, Pf*0.5, Pc*1.0, Po*0.5)  (0.5 = sigmoid-via-tanh prescale)
__device__ __align__(16) float g_proj2[4096 * 32 * 4];
// Rpack: ull at ((c*16 + j)*32 + lane) = (R[2j][col]*s_c, R[2j+1][col]*s_c), col = c*32+lane
__device__ __align__(16) unsigned long long g_R[4 * 16 * 32];

// ---------- packed f32x2 helpers ----------
__device__ __forceinline__ void fma2(unsigned long long& acc, unsigned long long a, unsigned long long b) {
    asm("fma.rn.f32x2 %0, %1, %2, %0;" : "+l"(acc) : "l"(a), "l"(b));
}
__device__ __forceinline__ unsigned long long pk2(float lo, float hi) {
    unsigned long long r;
    asm("mov.b64 %0, {%1, %2};" : "=l"(r) : "f"(lo), "f"(hi));
    return r;
}
__device__ __forceinline__ void unpk2(unsigned long long v, float& lo, float& hi) {
    asm("mov.b64 {%0, %1}, %2;" : "=f"(lo), "=f"(hi) : "l"(v));
}
// ---------- MUFU tanh (sm_75+) ----------
__device__ __forceinline__ float ftanh(float x) {
    float y; asm("tanh.approx.f32 %0, %1;" : "=f"(y) : "f"(x)); return y;
}

// ---------- merged prep ----------
__global__ void prep_all(const float* __restrict__ emb, const float* __restrict__ K,
                         const float* __restrict__ R, int nbuckets) {
    int idx = blockIdx.x * blockDim.x + threadIdx.x;
    // pack rec_kernel: 2048 entries (c, j, lane)
    if (idx < 4 * 16 * 32) {
        int lane = idx & 31, j = (idx >> 5) & 15, c = idx >> 9;
        int col = c * 32 + lane;
        float s = (c == 2) ? 1.0f : 0.5f;
        float lo = R[(2 * j) * 128 + col] * s;
        float hi = R[(2 * j + 1) * 128 + col] * s;
        g_R[idx] = *(unsigned long long*)&(float2){lo, hi};
    }
    // per-bucket projection table
    int id = idx >> 5, l = idx & 31;
    if (id >= nbuckets) return;
    float a = 0.f, b = 0.f, c = 0.f, d = 0.f;
#pragma unroll
    for (int e = 0; e < 16; e++) {
        float xv = emb[id * 16 + e];
        const float* kr = K + e * 128 + l;
        a = fmaf(xv, kr[0],  a);
        b = fmaf(xv, kr[32], b);
        c = fmaf(xv, kr[64], c);
        d = fmaf(xv, kr[96], d);
    }
    *(float4*)&g_proj2[idx * 4] = make_float4(a * 0.5f, b * 0.5f, c, d * 0.5f);
}

// ---------- main: warp-per-batch LSTM scan + fused head, 4 CTAs/SM ----------
__global__ __launch_bounds__(128, 4) void lstm_main(
    const int* __restrict__ ids,
    const float* __restrict__ w1, const float* __restrict__ b1,
    const float* __restrict__ w2, const float* __restrict__ b2,
    float* __restrict__ out, int B)
{
    __shared__ __align__(16) float hb[4][2][32];   // per-warp double-buffered h
    const int w = threadIdx.x >> 5;
    const int lane = threadIdx.x & 31;
    const int b = blockIdx.x * 4 + w;
    if (b >= B) return;   // uniform per warp

    // weights: per lane, 4 owned cols x 16 j-pairs (prescaled)
    unsigned long long RW[4][16];
#pragma unroll
    for (int c = 0; c < 4; c++)
#pragma unroll
        for (int j = 0; j < 16; j++)
            RW[c][j] = g_R[(c * 16 + j) * 32 + lane];

    const float4* Pp = (const float4*)g_proj2;
    const int* idrow = ids + b * T_STEPS;
    int idreg = idrow[lane];                              // ids for steps 0..31
    int id0 = __shfl_sync(0xffffffffu, idreg, 0);
    float4 p = Pp[id0 * 32 + lane];                       // proj for step 0 (prescaled)

    hb[w][0][lane] = 0.f;                                 // h_0 = 0
    __syncwarp();

    float cst = 0.f;
    for (int t = 0; t < T_STEPS; t++) {
        // prefetch proj for step t+1 (hidden behind this step's math)
        int tn = t + 1;
        if (((tn & 31) == 0) && (tn < T_STEPS)) idreg = idrow[tn + lane];
        int idn = __shfl_sync(0xffffffffu, idreg, tn & 31);
        float4 pn = Pp[idn * 32 + lane];

        // proj folded into acc init (even-half), saving FADDs in the tail
        unsigned long long a0 = pk2(p.x, 0.f);
        unsigned long long a1 = pk2(p.y, 0.f);
        unsigned long long a2 = pk2(p.z, 0.f);
        unsigned long long a3 = pk2(p.w, 0.f);
        const ulonglong2* hp = (const ulonglong2*)&hb[w][t & 1][0];
#pragma unroll
        for (int k = 0; k < 8; k++) {
            ulonglong2 hv = hp[k];              // (h4k,h4k+1),(h4k+2,h4k+3) broadcast LDS.128
            fma2(a0, RW[0][2 * k], hv.x);
            fma2(a1, RW[1][2 * k], hv.x);
            fma2(a2, RW[2][2 * k], hv.x);
            fma2(a3, RW[3][2 * k], hv.x);
            fma2(a0, RW[0][2 * k + 1], hv.y);
            fma2(a1, RW[1][2 * k + 1], hv.y);
            fma2(a2, RW[2][2 * k + 1], hv.y);
            fma2(a3, RW[3][2 * k + 1], hv.y);
        }
        float e0, o0, e1, o1, e2, o2, e3, o3;
        unpk2(a0, e0, o0); unpk2(a1, e1, o1); unpk2(a2, e2, o2); unpk2(a3, e3, o3);
        float zi = e0 + o0;
        float zf = e1 + o1;
        float zc = e2 + o2;
        float zo = e3 + o3;

        float ig = fmaf(ftanh(zi), 0.5f, 0.5f);   // sigmoid via tanh (prescaled x0.5)
        float fg = fmaf(ftanh(zf), 0.5f, 0.5f);
        float og = fmaf(ftanh(zo), 0.5f, 0.5f);
        float gg = ftanh(zc);
        cst = fmaf(fg, cst, ig * gg);
        float h = og * ftanh(cst);

        hb[w][tn & 1][lane] = h;
        __syncwarp();
        p = pn;
    }

    // head: y = relu(h @ w1 + b1) @ w2 + b2  (h lives in hb[w][0])
    float s = b1[lane];
#pragma unroll
    for (int l = 0; l < 32; l++)
        s = fmaf(hb[w][0][l], w1[l * 32 + lane], s);
    float r = fmaxf(s, 0.f) * w2[lane];
#pragma unroll
    for (int off = 16; off; off >>= 1)
        r += __shfl_xor_sync(0xffffffffu, r, off);
    if (lane == 0) out[b] = r + b2[0];
}

extern "C" void kernel_launch(void* const* d_in, const int* in_sizes, int n_in,
                              void* d_out, int out_size)
{
    const int*   ids  = (const int*)d_in[0];
    const float* emb  = (const float*)d_in[1];
    const float* kern = (const float*)d_in[2];
    const float* rec  = (const float*)d_in[3];
    const float* w1   = (const float*)d_in[4];
    const float* b1   = (const float*)d_in[5];
    const float* w2   = (const float*)d_in[6];
    const float* b2   = (const float*)d_in[7];

    int B = in_sizes[0] / T_STEPS;
    int nbuckets = in_sizes[1] / 16;
    if (nbuckets > 4096) nbuckets = 4096;

    int prep_threads = nbuckets * 32;
    if (prep_threads < 2048) prep_threads = 2048;
    prep_all<<<(prep_threads + 127) / 128, 128>>>(emb, kern, rec, nbuckets);
    lstm_main<<<(B + 3) / 4, 128>>>(ids, w1, b1, w2, b2, (float*)d_out, B);
}

// round 6
// speedup vs baseline: 1.5459x; 1.5459x over previous
#include <cuda_runtime.h>
#include <cstdint>

#define T_STEPS 512

// Scratch (allocation-free rule: __device__ globals)
// projP[(id*2+gh)*32+lane] : gh0 = (Pi*0.5, Pf*0.5), gh1 = (Pc, Po*0.5)
__device__ __align__(16) float2 g_projP[4096 * 2 * 32];
// R2[((cc)*16+jp)*32+lane] = (R[2jp][col]*s, R[2jp+1][col]*s), col = cc*32+lane, s = (cc==2?1:0.5)
__device__ __align__(16) unsigned long long g_R2[4 * 16 * 32];

// ---------- packed f32x2 helpers ----------
__device__ __forceinline__ void fma2(unsigned long long& acc, unsigned long long a, unsigned long long b) {
    asm("fma.rn.f32x2 %0, %1, %2, %0;" : "+l"(acc) : "l"(a), "l"(b));
}
__device__ __forceinline__ unsigned long long pk2(float lo, float hi) {
    unsigned long long r;
    asm("mov.b64 %0, {%1, %2};" : "=l"(r) : "f"(lo), "f"(hi));
    return r;
}
__device__ __forceinline__ void unpk2(unsigned long long v, float& lo, float& hi) {
    asm("mov.b64 {%0, %1}, %2;" : "=f"(lo), "=f"(hi) : "l"(v));
}
__device__ __forceinline__ float ftanh(float x) {
    float y; asm("tanh.approx.f32 %0, %1;" : "=f"(y) : "f"(x)); return y;
}
__device__ __forceinline__ float sigp(float xs) {  // sigmoid, input prescaled x0.5
    return fmaf(ftanh(xs), 0.5f, 0.5f);
}
#define TEAM_BAR(tm) asm volatile("bar.sync %0, 64;" :: "r"((tm) + 1) : "memory")

// ---------- merged prep ----------
__global__ void prep_all(const float* __restrict__ emb, const float* __restrict__ K,
                         const float* __restrict__ R, int nbuckets) {
    int idx = blockIdx.x * blockDim.x + threadIdx.x;
    // pack rec_kernel: 2048 entries (cc, jp, lane); cc = gate index 0..3 (i,f,c,o)
    if (idx < 4 * 16 * 32) {
        int lane = idx & 31, jp = (idx >> 5) & 15, cc = idx >> 9;
        int col = cc * 32 + lane;
        float s = (cc == 2) ? 1.0f : 0.5f;
        float lo = R[(2 * jp) * 128 + col] * s;
        float hi = R[(2 * jp + 1) * 128 + col] * s;
        g_R2[idx] = pk2(lo, hi);
    }
    // per-bucket projection table (two float2 halves per bucket-lane)
    int id = idx >> 5, l = idx & 31;
    if (id >= nbuckets) return;
    float a = 0.f, b = 0.f, c = 0.f, d = 0.f;
#pragma unroll
    for (int e = 0; e < 16; e++) {
        float xv = emb[id * 16 + e];
        const float* kr = K + e * 128 + l;
        a = fmaf(xv, kr[0],  a);
        b = fmaf(xv, kr[32], b);
        c = fmaf(xv, kr[64], c);
        d = fmaf(xv, kr[96], d);
    }
    g_projP[(id * 2 + 0) * 32 + l] = make_float2(a * 0.5f, b * 0.5f);
    g_projP[(id * 2 + 1) * 32 + l] = make_float2(c, d * 0.5f);
}

// ---------- main: 2-warp team per 2 batch rows; weights amortized (64 regs/lane) ----------
__global__ __launch_bounds__(128, 4) void lstm_main(
    const int* __restrict__ ids,
    const float* __restrict__ w1, const float* __restrict__ b1,
    const float* __restrict__ w2, const float* __restrict__ b2,
    float* __restrict__ out, int B)
{
    __shared__ __align__(16) float  hsm[2][64];      // [team][rowA h | rowB h]
    __shared__ __align__(16) float2 zb[2][2][32];    // [team][dir][lane] gate exchange
    const int w    = threadIdx.x >> 5;
    const int lane = threadIdx.x & 31;
    const int tm   = w >> 1;      // team in CTA
    const int gh   = w & 1;       // 0: gates i,f   1: gates c,o
    const int rowA = blockIdx.x * 4 + tm * 2;
    const int rowB = rowA + 1;
    if (rowA >= B) return;        // uniform per team (both warps together)

    // weights for this warp's 2 gate-columns (cc = gh*2, gh*2+1), 16 j-pairs each
    unsigned long long RW0[16], RW1[16];
#pragma unroll
    for (int jp = 0; jp < 16; jp++) {
        RW0[jp] = g_R2[((gh * 2 + 0) * 16 + jp) * 32 + lane];
        RW1[jp] = g_R2[((gh * 2 + 1) * 16 + jp) * 32 + lane];
    }

    const float2* Pp = g_projP;
    const int* idrowA = ids + rowA * T_STEPS;
    const int* idrowB = ids + rowB * T_STEPS;
    int idA = idrowA[lane];
    int idB = idrowB[lane];
    float2 pA = Pp[(__shfl_sync(0xffffffffu, idA, 0) * 2 + gh) * 32 + lane];
    float2 pB = Pp[(__shfl_sync(0xffffffffu, idB, 0) * 2 + gh) * 32 + lane];

    hsm[tm][gh * 32 + lane] = 0.f;   // h_0 = 0 (each warp inits its half)
    TEAM_BAR(tm);

    float cS = 0.f;                  // cell state: row A in warp gh0, row B in gh1
    for (int t = 0; t < T_STEPS; t++) {
        int tn = t + 1;
        if (((tn & 31) == 0) && (tn < T_STEPS)) {
            idA = idrowA[tn + lane];
            idB = idrowB[tn + lane];
        }
        int iA = __shfl_sync(0xffffffffu, idA, tn & 31);
        int iB = __shfl_sync(0xffffffffu, idB, tn & 31);
        float2 pnA = Pp[(iA * 2 + gh) * 32 + lane];
        float2 pnB = Pp[(iB * 2 + gh) * 32 + lane];

        // 4 chains: (gate0,gate1) x (rowA,rowB); proj folded into even-half init
        unsigned long long aA0 = pk2(pA.x, 0.f), aA1 = pk2(pA.y, 0.f);
        unsigned long long aB0 = pk2(pB.x, 0.f), aB1 = pk2(pB.y, 0.f);
        const ulonglong2* hpA = (const ulonglong2*)&hsm[tm][0];
        const ulonglong2* hpB = (const ulonglong2*)&hsm[tm][32];
#pragma unroll
        for (int k = 0; k < 8; k++) {
            ulonglong2 hvA = hpA[k];     // broadcast LDS.128: (h4k,h4k+1),(h4k+2,h4k+3)
            ulonglong2 hvB = hpB[k];
            fma2(aA0, RW0[2 * k], hvA.x);
            fma2(aA1, RW1[2 * k], hvA.x);
            fma2(aB0, RW0[2 * k], hvB.x);
            fma2(aB1, RW1[2 * k], hvB.x);
            fma2(aA0, RW0[2 * k + 1], hvA.y);
            fma2(aA1, RW1[2 * k + 1], hvA.y);
            fma2(aB0, RW0[2 * k + 1], hvB.y);
            fma2(aB1, RW1[2 * k + 1], hvB.y);
        }
        float lo, hi;
        unpk2(aA0, lo, hi); float zA0 = lo + hi;   // gh0: ziA  | gh1: zcA
        unpk2(aA1, lo, hi); float zA1 = lo + hi;   // gh0: zfA  | gh1: zoA
        unpk2(aB0, lo, hi); float zB0 = lo + hi;   // gh0: ziB  | gh1: zcB
        unpk2(aB1, lo, hi); float zB1 = lo + hi;   // gh0: zfB  | gh1: zoB

        // exchange the halves the partner warp needs
        if (gh == 0) zb[tm][0][lane] = make_float2(zB0, zB1);   // (ziB, zfB) -> warp1
        else         zb[tm][1][lane] = make_float2(zA0, zA1);   // (zcA, zoA) -> warp0
        TEAM_BAR(tm);

        float hN;
        if (gh == 0) {          // row A tail
            float2 q = zb[tm][1][lane];      // (zcA, zoA)
            float ig = sigp(zA0);
            float fg = sigp(zA1);
            float gg = ftanh(q.x);
            float og = sigp(q.y);
            cS = fmaf(fg, cS, ig * gg);
            hN = og * ftanh(cS);
        } else {                // row B tail
            float2 q = zb[tm][0][lane];      // (ziB, zfB)
            float ig = sigp(q.x);
            float fg = sigp(q.y);
            float gg = ftanh(zB0);
            float og = sigp(zB1);
            cS = fmaf(fg, cS, ig * gg);
            hN = og * ftanh(cS);
        }
        hsm[tm][gh * 32 + lane] = hN;
        TEAM_BAR(tm);
        pA = pnA;
        pB = pnB;
    }

    // head: warp gh0 -> row A from hsm[tm][0..31]; gh1 -> row B from hsm[tm][32..63]
    const float* hrow = &hsm[tm][gh * 32];
    float s = b1[lane];
#pragma unroll
    for (int l = 0; l < 32; l++)
        s = fmaf(hrow[l], w1[l * 32 + lane], s);
    float r = fmaxf(s, 0.f) * w2[lane];
#pragma unroll
    for (int off = 16; off; off >>= 1)
        r += __shfl_xor_sync(0xffffffffu, r, off);
    if (lane == 0) out[gh ? rowB : rowA] = r + b2[0];
}

extern "C" void kernel_launch(void* const* d_in, const int* in_sizes, int n_in,
                              void* d_out, int out_size)
{
    const int*   ids  = (const int*)d_in[0];
    const float* emb  = (const float*)d_in[1];
    const float* kern = (const float*)d_in[2];
    const float* rec  = (const float*)d_in[3];
    const float* w1   = (const float*)d_in[4];
    const float* b1   = (const float*)d_in[5];
    const float* w2   = (const float*)d_in[6];
    const float* b2   = (const float*)d_in[7];

    int B = in_sizes[0] / T_STEPS;
    int nbuckets = in_sizes[1] / 16;
    if (nbuckets > 4096) nbuckets = 4096;

    int prep_threads = nbuckets * 32;
    if (prep_threads < 2048) prep_threads = 2048;
    prep_all<<<(prep_threads + 127) / 128, 128>>>(emb, kern, rec, nbuckets);
    lstm_main<<<(B + 3) / 4, 128>>>(ids, w1, b1, w2, b2, (float*)d_out, B);
}